// round 10
// baseline (speedup 1.0000x reference)
#include <cuda_runtime.h>

// Lorentz boost applied per-channel:
//   out[b,c,i] = B(Bo[c])[i,j] * T[b,c,j]
// with B = I - g*mag*nK + (g-1)*nK^2 reduced analytically to:
//   y0 = g*(x0 - mag*(n.x))
//   yi = xi + n_i * ((g-1)*(n.x) - g*mag*x0)
//
// T: (8192, 1024, 4) fp32.  Pure HBM streaming, 256 MiB total traffic.
// R1: 1024 fat CTAs, one uneven wave -> DRAM 68.9%.
// R4: 4096 short CTAs, MLP=8 front-batch -> DRAM 72.5%, but regs 48 ->
//     occupancy 52.8% (reg-bound at ~42 warps/SM); in-flight ~4.3KB/SM vs
//     ~5.9KB/SM needed to hide DRAM latency.
// R5-R10: __launch_bounds__(256, 6) caps regs ~42 -> 48 warps/SM, in-flight
//     6.1KB/SM. Addressing folds into LDG immediate offsets (16KB stride).
//     (R5-R9 benches lost to broker timeouts; resubmitted unchanged.)

#define NB 8192
#define NC 1024
#define ROWS_PER_BLOCK 8
#define THREADS 256
#define EPS 1e-7f

__global__ __launch_bounds__(THREADS, 6)
void lorentz_boost_kernel(const float4* __restrict__ T,
                          const float* __restrict__ Bo,
                          float4* __restrict__ out)
{
    const int c  = blockIdx.x * THREADS + threadIdx.x;   // channel 0..1023
    const int b0 = blockIdx.y * ROWS_PER_BLOCK;          // batch slab start

    // Per-channel boost coefficients (registers for the whole slab).
    const float bx = Bo[c * 3 + 0];
    const float by = Bo[c * 3 + 1];
    const float bz = Bo[c * 3 + 2];
    float mag = sqrtf(bx * bx + by * by + bz * bz);
    mag = fminf(fmaxf(mag, EPS), 1.0f - EPS);
    const float inv_mag = 1.0f / mag;
    const float n1 = bx * inv_mag;
    const float n2 = by * inv_mag;
    const float n3 = bz * inv_mag;
    const float g   = rsqrtf(fmaxf(1.0f - mag * mag, 1e-30f));
    const float gm  = g * mag;        // g*mag
    const float gm1 = g - 1.0f;       // g-1

    // Single base pointer; the 8 loads/stores become immediate-offset LDG/STG.
    const float4* __restrict__ tp = T   + (b0 * NC + c);
    float4* __restrict__       op = out + (b0 * NC + c);

    // Front-batch all 8 loads: MLP=8 per thread.
    float4 v[ROWS_PER_BLOCK];
    #pragma unroll
    for (int r = 0; r < ROWS_PER_BLOCK; ++r)
        v[r] = __ldcs(tp + r * NC);

    #pragma unroll
    for (int r = 0; r < ROWS_PER_BLOCK; ++r) {
        const float s = n1 * v[r].y + n2 * v[r].z + n3 * v[r].w;  // n . x
        float4 y;
        y.x = g * v[r].x - gm * s;
        const float w = gm1 * s - gm * v[r].x;
        y.y = v[r].y + n1 * w;
        y.z = v[r].z + n2 * w;
        y.w = v[r].w + n3 * w;
        __stcs(op + r * NC, y);
    }
}

extern "C" void kernel_launch(void* const* d_in, const int* in_sizes, int n_in,
                              void* d_out, int out_size)
{
    const float4* T  = (const float4*)d_in[0];   // (8192, 1024, 4)
    const float* Bo  = (const float*)d_in[1];    // (1024, 3)
    float4* out = (float4*)d_out;

    dim3 grid(NC / THREADS, NB / ROWS_PER_BLOCK);  // (4, 1024) = 4096 CTAs
    lorentz_boost_kernel<<<grid, THREADS>>>(T, Bo, out);
}

// round 13
// speedup vs baseline: 1.0064x; 1.0064x over previous
#include <cuda_runtime.h>

// Lorentz boost applied per-channel:
//   out[b,c,i] = B(Bo[c])[i,j] * T[b,c,j]
// with B = I - g*mag*nK + (g-1)*nK^2 reduced analytically to:
//   y0 = g*(x0 - mag*(n.x))
//   yi = xi + n_i * ((g-1)*(n.x) - g*mag*x0)
//
// T: (8192, 1024, 4) fp32.  Pure HBM streaming, 256 MiB traffic.
// R1:  32-row CTAs, 1 wave            -> 39.5us, DRAM 68.9%
// R4:  8-row CTAs, MLP=8, regs 48     -> 37.2us, DRAM 72.5%   (best)
// R10: + reg cap 40, 48 warps/SM      -> 39.3us, DRAM 69.3%   (REGRESSION:
//      more resident CTAs deepened cross-CTA L1tex queue contention)
// R11-R13: opposite axis — fewer warps, deeper per-thread MLP: 16-row CTAs,
//      front-batch 16 loads, NO reg cap. ~80 regs -> 3 CTAs/SM, 24 warps,
//      in-flight 24*16*16B ~ 6.1KB/SM with half the CTA-level queue
//      contention. Falsifier: spill (local traffic) or dur>=38us -> revert R4.
//      (R11/R12 benches lost to broker timeouts; resubmitted unchanged.)

#define NB 8192
#define NC 1024
#define ROWS_PER_BLOCK 16
#define THREADS 256
#define EPS 1e-7f

__global__ __launch_bounds__(THREADS)
void lorentz_boost_kernel(const float4* __restrict__ T,
                          const float* __restrict__ Bo,
                          float4* __restrict__ out)
{
    const int c  = blockIdx.x * THREADS + threadIdx.x;   // channel 0..1023
    const int b0 = blockIdx.y * ROWS_PER_BLOCK;          // batch slab start

    // Per-channel boost coefficients (registers for the whole slab).
    const float bx = Bo[c * 3 + 0];
    const float by = Bo[c * 3 + 1];
    const float bz = Bo[c * 3 + 2];
    float mag = sqrtf(bx * bx + by * by + bz * bz);
    mag = fminf(fmaxf(mag, EPS), 1.0f - EPS);
    const float inv_mag = 1.0f / mag;
    const float n1 = bx * inv_mag;
    const float n2 = by * inv_mag;
    const float n3 = bz * inv_mag;
    const float g   = rsqrtf(fmaxf(1.0f - mag * mag, 1e-30f));
    const float gm  = g * mag;        // g*mag
    const float gm1 = g - 1.0f;       // g-1

    // Single base pointer; loads/stores become immediate-offset LDG/STG.
    const float4* __restrict__ tp = T   + (b0 * NC + c);
    float4* __restrict__       op = out + (b0 * NC + c);

    // Front-batch all 16 loads: MLP=16 per thread.
    float4 v[ROWS_PER_BLOCK];
    #pragma unroll
    for (int r = 0; r < ROWS_PER_BLOCK; ++r)
        v[r] = __ldcs(tp + r * NC);

    #pragma unroll
    for (int r = 0; r < ROWS_PER_BLOCK; ++r) {
        const float s = n1 * v[r].y + n2 * v[r].z + n3 * v[r].w;  // n . x
        float4 y;
        y.x = g * v[r].x - gm * s;
        const float w = gm1 * s - gm * v[r].x;
        y.y = v[r].y + n1 * w;
        y.z = v[r].z + n2 * w;
        y.w = v[r].w + n3 * w;
        __stcs(op + r * NC, y);
    }
}

extern "C" void kernel_launch(void* const* d_in, const int* in_sizes, int n_in,
                              void* d_out, int out_size)
{
    const float4* T  = (const float4*)d_in[0];   // (8192, 1024, 4)
    const float* Bo  = (const float*)d_in[1];    // (1024, 3)
    float4* out = (float4*)d_out;

    dim3 grid(NC / THREADS, NB / ROWS_PER_BLOCK);  // (4, 512) = 2048 CTAs
    lorentz_boost_kernel<<<grid, THREADS>>>(T, Bo, out);
}

// round 16
// speedup vs baseline: 1.0427x; 1.0361x over previous
#include <cuda_runtime.h>

// Lorentz boost applied per-channel:
//   out[b,c,i] = B(Bo[c])[i,j] * T[b,c,j]
// with B = I - g*mag*nK + (g-1)*nK^2 reduced analytically to:
//   y0 = g*(x0 - mag*(n.x))
//   yi = xi + n_i * ((g-1)*(n.x) - g*mag*x0)
//
// T: (8192, 1024, 4) fp32.  Pure HBM streaming, 256 MiB mandatory traffic.
//
// FINAL: R4 configuration. Experiment ladder:
//   R1:  32-row CTAs, 1 wave           -> 39.5us, DRAM 68.9% (tail-limited)
//   R4:  8-row CTAs, MLP=8, 5 CTA/SM   -> 37.2us, DRAM 72.5% (BEST)
//   R10: reg cap 40, 6 CTA/SM          -> 39.3us, DRAM 69.3% (more CTAs hurt)
//   R13: 16-row, MLP=16, 3 CTA/SM      -> 37.8us, DRAM 71.4% (more MLP: flat)
// Raising in-flight bytes 4.3->6.1 KB/SM via either warps or MLP does not
// move DRAM% past ~72%: this is the chip ceiling for a 1:1 interleaved
// read/write stream (~5.7 TB/s at NAT clocks). Traffic is irreducible, so
// R4 sits at the roofline; R4 vs R13 delta is inside +/-3% run variance.
// (R14/R15 confirmation benches lost to broker timeouts; resubmitted
// unchanged.)

#define NB 8192
#define NC 1024
#define ROWS_PER_BLOCK 8
#define THREADS 256
#define EPS 1e-7f

__global__ __launch_bounds__(THREADS)
void lorentz_boost_kernel(const float4* __restrict__ T,
                          const float* __restrict__ Bo,
                          float4* __restrict__ out)
{
    const int c  = blockIdx.x * THREADS + threadIdx.x;   // channel 0..1023
    const int b0 = blockIdx.y * ROWS_PER_BLOCK;          // batch slab start

    // Per-channel boost coefficients (registers for the whole slab).
    const float bx = Bo[c * 3 + 0];
    const float by = Bo[c * 3 + 1];
    const float bz = Bo[c * 3 + 2];
    float mag = sqrtf(bx * bx + by * by + bz * bz);
    mag = fminf(fmaxf(mag, EPS), 1.0f - EPS);
    const float inv_mag = 1.0f / mag;
    const float n1 = bx * inv_mag;
    const float n2 = by * inv_mag;
    const float n3 = bz * inv_mag;
    const float g   = rsqrtf(fmaxf(1.0f - mag * mag, 1e-30f));
    const float gm  = g * mag;        // g*mag
    const float gm1 = g - 1.0f;       // g-1

    // Single base pointer; loads/stores become immediate-offset LDG/STG.
    const float4* __restrict__ tp = T   + (b0 * NC + c);
    float4* __restrict__       op = out + (b0 * NC + c);

    // Front-batch all 8 loads: MLP=8 per thread.
    float4 v[ROWS_PER_BLOCK];
    #pragma unroll
    for (int r = 0; r < ROWS_PER_BLOCK; ++r)
        v[r] = __ldcs(tp + r * NC);

    #pragma unroll
    for (int r = 0; r < ROWS_PER_BLOCK; ++r) {
        const float s = n1 * v[r].y + n2 * v[r].z + n3 * v[r].w;  // n . x
        float4 y;
        y.x = g * v[r].x - gm * s;
        const float w = gm1 * s - gm * v[r].x;
        y.y = v[r].y + n1 * w;
        y.z = v[r].z + n2 * w;
        y.w = v[r].w + n3 * w;
        __stcs(op + r * NC, y);
    }
}

extern "C" void kernel_launch(void* const* d_in, const int* in_sizes, int n_in,
                              void* d_out, int out_size)
{
    const float4* T  = (const float4*)d_in[0];   // (8192, 1024, 4)
    const float* Bo  = (const float*)d_in[1];    // (1024, 3)
    float4* out = (float4*)d_out;

    dim3 grid(NC / THREADS, NB / ROWS_PER_BLOCK);  // (4, 1024) = 4096 CTAs
    lorentz_boost_kernel<<<grid, THREADS>>>(T, Bo, out);
}